// round 8
// baseline (speedup 1.0000x reference)
#include <cuda_runtime.h>
#include <cstdint>

#define SIZE   128
#define EPSF   1e-6f
#define BW     4            // half bandwidth of final operators
#define TAPS   9            // 2*BW+1
#define CW     12           // padded Lb coeff row width
#define KBC    10           // chain band half-width (5-sweep products)
#define CBW    21           // chain band storage width
#define KBE    12           // E (10-sweep) band half-width
#define EW     25           // E band storage width
#define RSTRIP 64           // rows per band CTA
#define UROWS  (RSTRIP + 2 * BW)   // 72

// ---------------------------------------------------------------------------
// Globals
// ---------------------------------------------------------------------------
// banded chains: 0..3 = X chains C1..C4 (W = C1*C2*C3*C4), 4 = Q1, 5 = Q2 (L = Q2*Q1)
__device__ float g_cb[6][SIZE * CBW];
__device__ float g_Lb[SIZE * CW];          // row-major padded, per output row i
__device__ float g_WbT[TAPS * SIZE];       // tap-major: WbT[d][j] = W[j-BW+d][j]

// ---------------------------------------------------------------------------
// setup_ops: 6 CTAs. Coefficients in parallel, Thomas factors (5 lanes,
// rcp.approx), 5 register-light IN-PLACE solves on the identity, band extract.
// X chain part p covers X-order sweeps [5p,5p+5); m-th X sweep: k=m>>1,
// t=(k+(m&1))*DT, dt=DT/2. Y parts 4,5: m-th Y sweep t=m*DT+DT/2, dt=DT.
// ---------------------------------------------------------------------------
__device__ void solve_vec_ip(float* tile, int base, int stp,
                             const float* cf, const float* fI, const float* fN) {
    float dp = tile[base] * fI[0];
    tile[base] = dp;
    #pragma unroll 1
    for (int i = 1; i < SIZE; i++) {
        dp = fmaf(cf[i], dp, tile[base + i * stp]) * fI[i];
        tile[base + i * stp] = dp;          // ds_i stored in place
    }
    float x = dp;                            // x[127] = ds[127] already stored
    #pragma unroll 1
    for (int i = SIZE - 2; i >= 0; i--) {
        x = fmaf(fN[i], x, tile[base + i * stp]);
        tile[base + i * stp] = x;
    }
}

__global__ void __launch_bounds__(128, 1)
setup_ops_kernel(const float* __restrict__ abx, const float* __restrict__ atx,
                 const float* __restrict__ aqx, const float* __restrict__ bby,
                 const float* __restrict__ bty, const float* __restrict__ bqy)
{
    extern __shared__ float sh[];
    float* tile = sh;                        // 128*129
    float* co   = sh + SIZE * 129;           // 5*128 coeff (= -a = -c offdiag)
    float* fI   = co + 5 * SIZE;             // 5*128 1/dn
    float* fN   = fI + 5 * SIZE;             // 5*128 -c_star

    const int tid  = threadIdx.x;
    const int part = blockIdx.x;
    const bool isY = part >= 4;

    #pragma unroll 1
    for (int q = 0; q < 5; q++) {
        int m = isY ? (part - 4) * 5 + q : part * 5 + q;
        float t, dt; const float *bp, *lp, *qp;
        if (isY) { t = m * 0.01f + 0.005f;                    dt = 0.01f;  bp = bby; lp = bty; qp = bqy; }
        else     { int k = m >> 1; t = (k + (m & 1)) * 0.01f; dt = 0.005f; bp = abx; lp = atx; qp = aqx; }
        int i = tid;
        int im = max(i - 1, 0), ip = min(i + 1, 127);
        float vm = fmaxf(bp[im] + lp[im] * t + qp[im] * t * t, EPSF);
        float vc = fmaxf(bp[i]  + lp[i]  * t + qp[i]  * t * t, EPSF);
        float vp = fmaxf(bp[ip] + lp[ip] * t + qp[ip] * t * t, EPSF);
        co[q * SIZE + i] = (vm + vc + vp) * (1.0f / 3.0f) * dt;
    }
    for (int i = tid; i < SIZE * SIZE; i += 128)
        tile[(i >> 7) * 129 + (i & 127)] = ((i >> 7) == (i & 127)) ? 1.0f : 0.0f;
    __syncthreads();

    if (tid < 5) {
        const float* c = &co[tid * SIZE];
        float cs_prev = 0.0f;
        for (int i = 0; i < SIZE; i++) {
            float ci = c[i];
            float bi = (i == 0 || i == SIZE - 1) ? (1.0f + ci) : (1.0f + 2.0f * ci);
            float dn = bi + ci * cs_prev + EPSF;
            float inv;
            asm("rcp.approx.f32 %0, %1;" : "=f"(inv) : "f"(dn));
            float cs = -ci * inv;
            fI[tid * SIZE + i] = inv;
            fN[tid * SIZE + i] = -cs;
            cs_prev = cs;
        }
    }
    __syncthreads();

    const int base = isY ? tid : tid * 129;
    const int stp  = isY ? 129 : 1;
    #pragma unroll 1
    for (int q = 0; q < 5; q++)
        solve_vec_ip(tile, base, stp, &co[q * SIZE], &fI[q * SIZE], &fN[q * SIZE]);
    __syncthreads();

    const int r = tid;
    for (int d = 0; d < CBW; d++) {
        int c = r - KBC + d;
        g_cb[part][r * CBW + d] = (c >= 0 && c < SIZE) ? tile[r * 129 + c] : 0.0f;
    }
}

// ---------------------------------------------------------------------------
// setup3: band composition in one 1024-thread CTA.
// E1 = C1*C2, E2 = C3*C4 (band KBE); Lb = band_BW(Q2*Q1); WbT = band_BW(E1*E2)^T.
// ---------------------------------------------------------------------------
__global__ void __launch_bounds__(1024, 1) setup3_kernel()
{
    extern __shared__ float s3[];
    float* cb = s3;                      // 6*128*21
    float* E  = s3 + 6 * SIZE * CBW;     // 2*128*25
    const int tid = threadIdx.x;

    for (int m = tid; m < 6 * SIZE * CBW; m += 1024)
        cb[m] = ((const float*)g_cb)[m];
    __syncthreads();

    for (int idx = tid; idx < 2 * SIZE * EW; idx += 1024) {
        int e = idx / (SIZE * EW);
        int rem = idx - e * (SIZE * EW);
        int r = rem / EW, d = rem - r * EW;
        int c = r - KBE + d;
        float s = 0.0f;
        if (c >= 0 && c < SIZE) {
            const float* A = cb + (2 * e)     * SIZE * CBW;
            const float* B = cb + (2 * e + 1) * SIZE * CBW;
            int klo = max(max(r, c) - KBC, 0), khi = min(min(r, c) + KBC, 127);
            for (int k = klo; k <= khi; k++)
                s += A[r * CBW + (k - r + KBC)] * B[k * CBW + (c - k + KBC)];
        }
        E[idx] = s;
    }

    // Lb[i][d] = (Q2*Q1)[i][i-BW+d], padded to CW
    for (int idx = tid; idx < SIZE * CW; idx += 1024) {
        int i = idx / CW, d = idx - i * CW;
        float s = 0.0f;
        if (d < TAPS) {
            int c = i - BW + d;
            if (c >= 0 && c < SIZE) {
                const float* Q2 = cb + 5 * SIZE * CBW;
                const float* Q1 = cb + 4 * SIZE * CBW;
                int klo = max(max(i, c) - KBC, 0), khi = min(min(i, c) + KBC, 127);
                for (int k = klo; k <= khi; k++)
                    s += Q2[i * CBW + (k - i + KBC)] * Q1[k * CBW + (c - k + KBC)];
            }
        }
        g_Lb[idx] = s;
    }
    __syncthreads();

    // WbT[d][j] = (E1*E2)[j-BW+d][j]
    for (int idx = tid; idx < SIZE * TAPS; idx += 1024) {
        int d = idx / SIZE, j = idx - d * SIZE;
        float s = 0.0f;
        int r = j - BW + d;
        if (r >= 0 && r < SIZE) {
            const float* E1 = E, *E2 = E + SIZE * EW;
            int mlo = max(max(r, j) - KBE, 0), mhi = min(min(r, j) + KBE, 127);
            for (int m = mlo; m <= mhi; m++)
                s += E1[r * EW + (m - r + KBE)] * E2[m * EW + (j - m + KBE)];
        }
        g_WbT[idx] = s;
    }
}

// ---------------------------------------------------------------------------
// band_kernel: 2 CTAs per image (64-row strips), 256 threads, 8 rows/warp.
// u strip staged once to smem; per output row: 1 LDS.128 (register sliding
// window) + 3 warp-uniform Lb LDGs + 72 FMA + 8 SHFL + 1 STG.128.
// Wb held in 36 registers (tap-major LDG.128 at start).
// ---------------------------------------------------------------------------
__device__ __forceinline__ float4 f4fma(float c, float4 w, float4 a) {
    a.x = fmaf(c, w.x, a.x); a.y = fmaf(c, w.y, a.y);
    a.z = fmaf(c, w.z, a.z); a.w = fmaf(c, w.w, a.w);
    return a;
}

__global__ void __launch_bounds__(256, 2)
band_kernel(const float* __restrict__ uin, float* __restrict__ uout)
{
    __shared__ float us[UROWS * SIZE];       // 36864 B

    const int tid  = threadIdx.x, w = tid >> 5, lane = tid & 31;
    const int img  = blockIdx.x >> 1;
    const int r0   = (blockIdx.x & 1) * RSTRIP;
    const size_t off = (size_t)img * (SIZE * SIZE);
    const float* src = uin + off;

    // stage u strip rows [r0-4, r0+68) clamped
    #pragma unroll
    for (int q = 0; q < 9; q++) {
        int m = tid + q * 256;
        int r = m >> 5, c4 = (m & 31) * 4;
        int gr = min(max(r0 - BW + r, 0), SIZE - 1);
        *(float4*)&us[r * SIZE + c4] = *(const float4*)&src[gr * SIZE + c4];
    }

    // per-lane Wb registers, tap-major (cols 4*lane..4*lane+3 per tap)
    float4 wb4[TAPS];
    #pragma unroll
    for (int d = 0; d < TAPS; d++)
        wb4[d] = *(const float4*)&g_WbT[d * SIZE + 4 * lane];
    __syncthreads();

    const int il0 = w * 8;                   // window base: us rows il0..il0+8 = u rows gi-4..gi+4
    float4 win[TAPS];
    #pragma unroll
    for (int t = 0; t < TAPS - 1; t++)
        win[t] = *(const float4*)&us[(il0 + t) * SIZE + 4 * lane];

    float* dst = uout + off;
    #pragma unroll
    for (int rr = 0; rr < 8; rr++) {
        win[(rr + TAPS - 1) % TAPS] = *(const float4*)&us[(il0 + rr + TAPS - 1) * SIZE + 4 * lane];
        const int gi = r0 + il0 + rr;

        // ---- pass 1: T row (Lb warp-uniform LDG, L2-resident) ----
        const float* cr = &g_Lb[gi * CW];
        float4 c0 = *(const float4*)cr;
        float4 c1 = *(const float4*)(cr + 4);
        float  c8 = cr[8];
        float4 t4 = make_float4(0.f, 0.f, 0.f, 0.f);
        t4 = f4fma(c0.x, win[(rr + 0) % TAPS], t4);
        t4 = f4fma(c0.y, win[(rr + 1) % TAPS], t4);
        t4 = f4fma(c0.z, win[(rr + 2) % TAPS], t4);
        t4 = f4fma(c0.w, win[(rr + 3) % TAPS], t4);
        t4 = f4fma(c1.x, win[(rr + 4) % TAPS], t4);
        t4 = f4fma(c1.y, win[(rr + 5) % TAPS], t4);
        t4 = f4fma(c1.z, win[(rr + 6) % TAPS], t4);
        t4 = f4fma(c1.w, win[(rr + 7) % TAPS], t4);
        t4 = f4fma(c8,   win[(rr + 8) % TAPS], t4);

        // ---- pass 2: row stencil via shuffles (edges hit zero coeffs) ----
        float Tl[12];
        Tl[0] = __shfl_up_sync(0xffffffffu, t4.x, 1);
        Tl[1] = __shfl_up_sync(0xffffffffu, t4.y, 1);
        Tl[2] = __shfl_up_sync(0xffffffffu, t4.z, 1);
        Tl[3] = __shfl_up_sync(0xffffffffu, t4.w, 1);
        Tl[4] = t4.x; Tl[5] = t4.y; Tl[6] = t4.z; Tl[7] = t4.w;
        Tl[8]  = __shfl_down_sync(0xffffffffu, t4.x, 1);
        Tl[9]  = __shfl_down_sync(0xffffffffu, t4.y, 1);
        Tl[10] = __shfl_down_sync(0xffffffffu, t4.z, 1);
        Tl[11] = __shfl_down_sync(0xffffffffu, t4.w, 1);

        float4 o = make_float4(0.f, 0.f, 0.f, 0.f);
        #pragma unroll
        for (int d = 0; d < TAPS; d++) {
            o.x = fmaf(wb4[d].x, Tl[0 + d], o.x);
            o.y = fmaf(wb4[d].y, Tl[1 + d], o.y);
            o.z = fmaf(wb4[d].z, Tl[2 + d], o.z);
            o.w = fmaf(wb4[d].w, Tl[3 + d], o.w);
        }
        *(float4*)&dst[gi * SIZE + 4 * lane] = o;
    }
}

// ---------------------------------------------------------------------------
extern "C" void kernel_launch(void* const* d_in, const int* in_sizes, int n_in,
                              void* d_out, int out_size)
{
    const float* u   = (const float*)d_in[0];
    const float* abx = (const float*)d_in[1];
    const float* bby = (const float*)d_in[4];
    const float* atx = (const float*)d_in[5];
    const float* bty = (const float*)d_in[8];
    const float* aqx = (const float*)d_in[9];
    const float* bqy = (const float*)d_in[12];
    float* out = (float*)d_out;

    const int smem_so = (SIZE * 129 + 15 * SIZE) * (int)sizeof(float);          // 73728
    const int smem_s3 = (6 * SIZE * CBW + 2 * SIZE * EW) * (int)sizeof(float);  // 90112

    cudaFuncSetAttribute(setup_ops_kernel, cudaFuncAttributeMaxDynamicSharedMemorySize, smem_so);
    cudaFuncSetAttribute(setup3_kernel,    cudaFuncAttributeMaxDynamicSharedMemorySize, smem_s3);

    const int batch = out_size / (SIZE * SIZE);   // 2048

    setup_ops_kernel<<<6, 128, smem_so>>>(abx, atx, aqx, bby, bty, bqy);
    setup3_kernel<<<1, 1024, smem_s3>>>();
    band_kernel<<<batch * 2, 256>>>(u, out);
}